// round 6
// baseline (speedup 1.0000x reference)
#include <cuda_runtime.h>
#include <math.h>

#define HID   256
#define B_    16
#define T_    1024
#define S_    256
#define MMAX  5151
#define NSLOT 80
#define MARG  9.0f          // tanh(9) = 1 - 3e-8 : saturation margin (x500 units)

typedef unsigned long long u64;

// -------- scratch (static device globals; no runtime allocation) ----------
__device__ float g_density[MMAX + 32];
__device__ float g_dsum;
__device__ float g_ctxw[B_ * HID];
__device__ float g_init[B_ * MMAX + 32];
__device__ float g_partial[(size_t)B_ * NSLOT * T_ * 8];

struct Tiles {
    int nt;
    int n;
    short tb[120];
    short ta[120];
};

__device__ __forceinline__ float sigmoidf_(float x) { return 1.0f / (1.0f + expf(-x)); }
__device__ __forceinline__ float tanh_fast(float x) {
    float y; asm("tanh.approx.f32 %0, %1;" : "=f"(y) : "f"(x)); return y;
}
__device__ __forceinline__ u64 pk2(float lo, float hi) {
    u64 r; asm("mov.b64 %0, {%1, %2};" : "=l"(r) : "f"(lo), "f"(hi)); return r;
}
__device__ __forceinline__ void upk2(u64 v, float& lo, float& hi) {
    asm("mov.b64 {%0, %1}, %2;" : "=f"(lo), "=f"(hi) : "l"(v));
}
__device__ __forceinline__ void ffma2(u64& d, u64 a, u64 b) {
    asm("fma.rn.f32x2 %0, %1, %2, %0;" : "+l"(d) : "l"(a), "l"(b));
}
__device__ __forceinline__ float warp_min(float v) {
#pragma unroll
    for (int o = 16; o > 0; o >>= 1) v = fminf(v, __shfl_xor_sync(0xffffffffu, v, o));
    return v;
}
__device__ __forceinline__ float warp_max(float v) {
#pragma unroll
    for (int o = 16; o > 0; o >>= 1) v = fmaxf(v, __shfl_xor_sync(0xffffffffu, v, o));
    return v;
}

// ---------------- K1: density MLP with packed f32x2 FFMA -------------------
// 16 mesh rows/block as 8 row-pairs; 128 threads own 2 adjacent cols each.
// Activations in smem as float2 hP[pair][k] so a broadcast LDS.128 feeds
// 2 pairs x 2 k-steps of fma.rn.f32x2.
#define PADK 258
__global__ void __launch_bounds__(128)
k_density(const float* __restrict__ mesh,
          const float* __restrict__ Win, const float* __restrict__ bin,
          const float* __restrict__ Wr,  const float* __restrict__ br,
          const float* __restrict__ Wout,const float* __restrict__ bout,
          int M)
{
    __shared__ float2 hP[8][PADK];      // rows (2p,2p+1) at feature k
    __shared__ float  sB[16][128];
    const int tid = threadIdx.x;
    const int c0  = 2 * tid, c1 = c0 + 1;
    const int r0  = blockIdx.x * 16;

    // ---- input layer ----
    {
        float wa0 = Win[c0], wb0 = Win[HID + c0], bi0 = bin[c0];
        float wa1 = Win[c1], wb1 = Win[HID + c1], bi1 = bin[c1];
#pragma unroll
        for (int p = 0; p < 8; ++p) {
            float4 v;
            float be0 = 0.f, al0 = 0.f, be1 = 0.f, al1 = 0.f;
            int ra = r0 + 2 * p, rb = ra + 1;
            if (ra < M) { be0 = mesh[ra * 2]; al0 = mesh[ra * 2 + 1]; }
            if (rb < M) { be1 = mesh[rb * 2]; al1 = mesh[rb * 2 + 1]; }
            v.x = fmaxf(fmaf(be0, wa0, fmaf(al0, wb0, bi0)), 0.f);
            v.y = fmaxf(fmaf(be1, wa0, fmaf(al1, wb0, bi0)), 0.f);
            v.z = fmaxf(fmaf(be0, wa1, fmaf(al0, wb1, bi1)), 0.f);
            v.w = fmaxf(fmaf(be1, wa1, fmaf(al1, wb1, bi1)), 0.f);
            *(float4*)&hP[p][c0] = v;
        }
    }
    __syncthreads();

    // ---- residual layers ----
    for (int l = 0; l < 3; ++l) {
        u64 A0[8], A1[8];
        {
            float bb0 = br[l * HID + c0], bb1 = br[l * HID + c1];
            u64 p0 = pk2(bb0, bb0), p1 = pk2(bb1, bb1);
#pragma unroll
            for (int p = 0; p < 8; ++p) { A0[p] = p0; A1[p] = p1; }
        }
        const float* W = Wr + l * HID * HID;
#pragma unroll 2
        for (int k = 0; k < HID; k += 2) {
            float2 wA = *(const float2*)&W[k * HID + c0];         // (c0,c1) at k
            float2 wB = *(const float2*)&W[(k + 1) * HID + c0];   // (c0,c1) at k+1
            u64 wx0 = pk2(wA.x, wA.x), wy0 = pk2(wA.y, wA.y);
            u64 wx1 = pk2(wB.x, wB.x), wy1 = pk2(wB.y, wB.y);
#pragma unroll
            for (int p = 0; p < 8; ++p) {
                float4 h4 = *(const float4*)&hP[p][k];   // pair @ k, pair @ k+1
                u64 hk  = pk2(h4.x, h4.y);
                u64 hk1 = pk2(h4.z, h4.w);
                ffma2(A0[p], hk,  wx0);
                ffma2(A1[p], hk,  wy0);
                ffma2(A0[p], hk1, wx1);
                ffma2(A1[p], hk1, wy1);
            }
        }
        __syncthreads();
#pragma unroll
        for (int p = 0; p < 8; ++p) {
            float4 h4 = *(const float4*)&hP[p][c0];
            float a, b;
            upk2(A0[p], a, b);
            h4.x += fmaxf(a, 0.f); h4.y += fmaxf(b, 0.f);
            upk2(A1[p], a, b);
            h4.z += fmaxf(a, 0.f); h4.w += fmaxf(b, 0.f);
            *(float4*)&hP[p][c0] = h4;
        }
        __syncthreads();
    }

    // ---- output layer + sigmoid ----
    {
        float wo0 = Wout[c0], wo1 = Wout[c1];
#pragma unroll
        for (int p = 0; p < 8; ++p) {
            float4 h4 = *(const float4*)&hP[p][c0];
            sB[2 * p][tid]     = fmaf(h4.x, wo0, h4.z * wo1);
            sB[2 * p + 1][tid] = fmaf(h4.y, wo0, h4.w * wo1);
        }
    }
    __syncthreads();

    int warp = tid >> 5, lane = tid & 31;
    float bo = bout[0];
    for (int rr = warp; rr < 16; rr += 4) {
        float v = (sB[rr][lane] + sB[rr][lane + 32]) + (sB[rr][lane + 64] + sB[rr][lane + 96]);
#pragma unroll
        for (int o = 16; o > 0; o >>= 1) v += __shfl_xor_sync(0xffffffffu, v, o);
        if (lane == 0) {
            int row = r0 + rr;
            if (row < M) g_density[row] = sigmoidf_(v + bo);
        }
    }
}

// ---------------- K2: encoder ctx (+ fused dsum in block 0) ---------------
__global__ void k_ctx(const float* __restrict__ enc_in, const float* __restrict__ maskp,
                      const float* __restrict__ Ws, const float* __restrict__ bs,
                      const float* __restrict__ Wc, const float* __restrict__ bm,
                      int M)
{
    __shared__ float ctx_s[HID];
    __shared__ float red[256];
    int b = blockIdx.x, c = threadIdx.x;
    float w0 = Ws[c], w1 = Ws[HID + c], bb = bs[c];
    float acc = 0.f, msum = 0.f;
    for (int s = 0; s < S_; ++s) {
        float mk = maskp[b * S_ + s];
        float e0 = enc_in[(b * S_ + s) * 2];
        float e1 = enc_in[(b * S_ + s) * 2 + 1];
        float v  = fmaxf(fmaf(e0, w0, fmaf(e1, w1, bb)), 0.f);
        acc  = fmaf(v, mk, acc);
        msum += mk;
    }
    ctx_s[c] = acc / fmaxf(msum, 1.0f);
    __syncthreads();
    float cw = bm[c];
    for (int k = 0; k < HID; ++k) cw = fmaf(ctx_s[k], Wc[k * HID + c], cw);
    g_ctxw[b * HID + c] = cw;

    if (b == 0) {
        float s = 0.f;
        for (int i = c; i < M; i += 256) s += g_density[i];
        red[c] = s;
        __syncthreads();
        for (int o = 128; o > 0; o >>= 1) {
            if (c < o) red[c] += red[c + o];
            __syncthreads();
        }
        if (c == 0) g_dsum = red[0];
    }
}

// ---------------- K3: initial states (thread per (b,j)) -------------------
__global__ void __launch_bounds__(256)
k_init(const float* __restrict__ mesh,
       const float* __restrict__ Wm, const float* __restrict__ Wo,
       const float* __restrict__ bo,
       float* __restrict__ out_init, float* __restrict__ out_dens,
       float* __restrict__ out_mesh, int M)
{
    __shared__ float4 sw4[HID];
    __shared__ float  scw[HID];
    int tid = threadIdx.x;
    int b   = blockIdx.y;
    for (int i = tid; i < HID; i += 256) {
        sw4[i] = make_float4(Wm[i], Wm[HID + i], Wm[2 * HID + i], Wo[i]);
        scw[i] = g_ctxw[b * HID + i];
    }
    __syncthreads();

    int j = blockIdx.x * 256 + tid;
    if (j >= M) return;

    float be = mesh[j * 2], al = mesh[j * 2 + 1], de = g_density[j];
    float a0 = 0.f, a1 = 0.f, a2 = 0.f, a3 = 0.f;
#pragma unroll 4
    for (int c = 0; c < HID; c += 4) {
        float4 w; float z;
        w = sw4[c + 0]; z = fmaxf(fmaf(be, w.x, fmaf(al, w.y, fmaf(de, w.z, scw[c + 0]))), 0.f); a0 = fmaf(z, w.w, a0);
        w = sw4[c + 1]; z = fmaxf(fmaf(be, w.x, fmaf(al, w.y, fmaf(de, w.z, scw[c + 1]))), 0.f); a1 = fmaf(z, w.w, a1);
        w = sw4[c + 2]; z = fmaxf(fmaf(be, w.x, fmaf(al, w.y, fmaf(de, w.z, scw[c + 2]))), 0.f); a2 = fmaf(z, w.w, a2);
        w = sw4[c + 3]; z = fmaxf(fmaf(be, w.x, fmaf(al, w.y, fmaf(de, w.z, scw[c + 3]))), 0.f); a3 = fmaf(z, w.w, a3);
    }
    float is = tanhf((a0 + a1) + (a2 + a3) + bo[0]);
    int wg = b * M + j;
    g_init[wg]           = is;
    out_init[wg]         = is;
    out_dens[wg]         = de;
    out_mesh[wg * 2]     = be;
    out_mesh[wg * 2 + 1] = al;
}

// ---------------- K4: relay scan with warp-uniform zone skipping ----------
// Zones per step (state-independent): ALL-UP (acc=+sum_de), ALL-DOWN
// (acc=-sum_de), DEAD (acc unchanged), else per-point with single- or
// dual-band tanh. Lazy state application via `pend`.
__global__ void __launch_bounds__(256)
k_scan(const float* __restrict__ mesh, const float* __restrict__ dec, int M, Tiles tl)
{
    __shared__ float hs[T_];
    int tid = threadIdx.x, lane = tid & 31, warp = tid >> 5;
    int b = blockIdx.y, tg = blockIdx.x;

    for (int t = tid; t < T_; t += 256) hs[t] = dec[b * T_ + t] * 500.f;
    __syncthreads();

    int tile = tg * 8 + warp;
    if (tile >= tl.nt) return;

    const int n  = tl.n;
    const int tb = tl.tb[tile], ta = tl.ta[tile];

    float a5[3], b5[3], de[3], s[3];
    float amin = 1e30f, amax = -1e30f, bmin = 1e30f, bmax = -1e30f;
#pragma unroll
    for (int i = 0; i < 3; ++i) {
        int cell = lane + 32 * i;
        int rib = cell / 12, ria = cell - rib * 12;
        int ib = tb * 8 + rib, ia = ta * 12 + ria;
        if (ib < n && ia < n && ia >= ib) {
            int j = ib * n - (ib * (ib - 1)) / 2 + (ia - ib);
            float be = mesh[2 * j] * 500.f;
            float al = mesh[2 * j + 1] * 500.f;
            a5[i] = al; b5[i] = be;
            de[i] = g_density[j];
            s[i]  = g_init[b * M + j];
            amin = fminf(amin, al); amax = fmaxf(amax, al);
            bmin = fminf(bmin, be); bmax = fmaxf(bmax, be);
        } else {
            a5[i] = 4000.f; b5[i] = -4000.f; de[i] = 0.f; s[i] = 0.f;
        }
    }
    const float am = warp_min(amin) - MARG, aM = warp_max(amax) + MARG;
    const float bm = warp_min(bmin) - MARG, bM = warp_max(bmax) + MARG;

    // group sums (over lanes {l, l^8, l^16, l^24})
    float sd8 = (de[0] + de[1]) + de[2];
    sd8 += __shfl_xor_sync(0xffffffffu, sd8, 16);
    sd8 += __shfl_xor_sync(0xffffffffu, sd8, 8);
    float cur = fmaf(de[0], s[0], fmaf(de[1], s[1], de[2] * s[2]));
    cur += __shfl_xor_sync(0xffffffffu, cur, 16);
    cur += __shfl_xor_sync(0xffffffffu, cur, 8);

    float* outp = g_partial + ((size_t)(b * NSLOT + tile)) * (T_ * 8);
    int pend = 0;

    float ht = hs[0];
    for (int t = 0; t < T_; ++t) {
        float htn = (t + 1 < T_) ? hs[t + 1] : 0.f;
        if (ht > aM)      { pend =  1; cur =  sd8; }
        else if (ht < bm) { pend = -1; cur = -sd8; }
        else if (ht > bM && ht < am) { /* dead: cur unchanged */ }
        else {
            if (pend > 0)      { s[0] = 1.f;  s[1] = 1.f;  s[2] = 1.f; }
            else if (pend < 0) { s[0] = -1.f; s[1] = -1.f; s[2] = -1.f; }
            pend = 0;
            bool inA = (ht < aM) && (ht > am);
            bool inB = (ht < bM) && (ht > bm);
            float acc = 0.f;
            if (inA && inB) {
#pragma unroll
                for (int i = 0; i < 3; ++i) {
                    float wu = fmaf(0.5f, tanh_fast(ht - a5[i]), 0.5f);
                    float wd = fmaf(0.5f, tanh_fast(b5[i] - ht), 0.5f);
                    float sv = s[i];
                    sv = fmaf(wu,  1.0f - sv, sv);
                    sv = fmaf(wd, -1.0f - sv, sv);
                    s[i] = sv;
                    acc = fmaf(de[i], sv, acc);
                }
            } else if (inA) {
#pragma unroll
                for (int i = 0; i < 3; ++i) {
                    float wu = fmaf(0.5f, tanh_fast(ht - a5[i]), 0.5f);
                    float sv = s[i];
                    sv = fmaf(wu, 1.0f - sv, sv);
                    sv = (ht < b5[i]) ? -1.0f : sv;   // exact: outside beta band
                    s[i] = sv;
                    acc = fmaf(de[i], sv, acc);
                }
            } else {
#pragma unroll
                for (int i = 0; i < 3; ++i) {
                    float sv = s[i];
                    sv = (ht > a5[i]) ? 1.0f : sv;    // exact: outside alpha band
                    float wd = fmaf(0.5f, tanh_fast(b5[i] - ht), 0.5f);
                    sv = fmaf(wd, -1.0f - sv, sv);
                    s[i] = sv;
                    acc = fmaf(de[i], sv, acc);
                }
            }
            acc += __shfl_xor_sync(0xffffffffu, acc, 16);
            acc += __shfl_xor_sync(0xffffffffu, acc, 8);
            cur = acc;
        }
        if (lane < 8) outp[t * 8 + lane] = cur;
        ht = htn;
    }
}

// ---------------- K5: reduce partials, scales, b_out ----------------------
__global__ void k_final(const float* __restrict__ dec,
                        const float* __restrict__ hr, const float* __restrict__ mr,
                        const float* __restrict__ offr,
                        float* __restrict__ out_b, float* __restrict__ out_m,
                        int nt)
{
    int idx = blockIdx.x * 256 + threadIdx.x;
    int b = idx >> 10, t = idx & 1023;
    const float* base = g_partial + (size_t)b * NSLOT * (T_ * 8) + (size_t)t * 8;
    float s0 = 0.f, s1 = 0.f, s2 = 0.f, s3 = 0.f, s4 = 0.f, s5 = 0.f, s6 = 0.f, s7 = 0.f;
    for (int tile = 0; tile < nt; ++tile) {
        const float4* p = (const float4*)(base + (size_t)tile * (T_ * 8));
        float4 v0 = p[0], v1 = p[1];
        s0 += v0.x; s1 += v0.y; s2 += v0.z; s3 += v0.w;
        s4 += v1.x; s5 += v1.y; s6 += v1.z; s7 += v1.w;
    }
    float sum = ((s0 + s1) + (s2 + s3)) + ((s4 + s5) + (s6 + s7));
    float m = sum / g_dsum;

    float hsc = 10.f * sigmoidf_(hr[0]);
    float msc = 10.f * sigmoidf_(mr[0]);
    float mof = fmaf(20.f, sigmoidf_(offr[0]), -10.f);

    float hv = dec[idx];
    out_b[idx] = fmaf(hsc, hv, fmaf(msc, m, mof));
    out_m[idx] = m;
}

// ---------------- host launcher -------------------------------------------
extern "C" void kernel_launch(void* const* d_in, const int* in_sizes, int n_in,
                              void* d_out, int out_size)
{
    const float* enc_in = (const float*)d_in[0];
    const float* dec    = (const float*)d_in[1];
    const float* maskp  = (const float*)d_in[2];
    const float* mesh   = (const float*)d_in[3];
    const float* dWin   = (const float*)d_in[4];
    const float* dbin   = (const float*)d_in[5];
    const float* dWr    = (const float*)d_in[6];
    const float* dbr    = (const float*)d_in[7];
    const float* dWout  = (const float*)d_in[8];
    const float* dbout  = (const float*)d_in[9];
    const float* eWs    = (const float*)d_in[10];
    const float* ebs    = (const float*)d_in[11];
    const float* eWm    = (const float*)d_in[12];
    const float* eWc    = (const float*)d_in[13];
    const float* ebm    = (const float*)d_in[14];
    const float* eWo    = (const float*)d_in[15];
    const float* ebo    = (const float*)d_in[16];
    const float* hr     = (const float*)d_in[17];
    const float* mr     = (const float*)d_in[18];
    const float* offr   = (const float*)d_in[19];

    const int M = in_sizes[3] / 2;   // 5151

    int n = 2;
    while (n * (n + 1) / 2 < M) ++n;   // -> 101

    Tiles tl;
    tl.n = n;
    tl.nt = 0;
    int ntb = (n + 7) / 8, nta = (n + 11) / 12;
    for (int tb = 0; tb < ntb; ++tb)
        for (int ta = 0; ta < nta; ++ta) {
            int ibmin = tb * 8;
            int iamax = ta * 12 + 11; if (iamax > n - 1) iamax = n - 1;
            if (iamax < ibmin) continue;
            if (tl.nt < 120) { tl.tb[tl.nt] = (short)tb; tl.ta[tl.nt] = (short)ta; tl.nt++; }
        }
    if (tl.nt > NSLOT) tl.nt = NSLOT;
    int groups = (tl.nt + 7) / 8;

    float* out      = (float*)d_out;
    float* out_b    = out;
    float* out_dens = out_b    + B_ * T_;
    float* out_m    = out_dens + B_ * M;
    float* out_init = out_m    + B_ * T_;
    float* out_mesh = out_init + B_ * M;

    k_density<<<(M + 15) / 16, 128>>>(mesh, dWin, dbin, dWr, dbr, dWout, dbout, M);
    k_ctx<<<B_, 256>>>(enc_in, maskp, eWs, ebs, eWc, ebm, M);
    k_init<<<dim3((M + 255) / 256, B_), 256>>>(mesh, eWm, eWo, ebo, out_init, out_dens, out_mesh, M);
    k_scan<<<dim3(groups, B_), 256>>>(mesh, dec, M, tl);
    k_final<<<(B_ * T_) / 256, 256>>>(dec, hr, mr, offr, out_b, out_m, tl.nt);

    (void)n_in; (void)out_size;
}